// round 3
// baseline (speedup 1.0000x reference)
#include <cuda_runtime.h>

// Problem constants
#define B_   8
#define C_   512
#define L_   2048
#define CQ_  64
#define KW_  3
#define KK_  (C_ * KW_)   // 1536 = im2col K for the convs

// Scratch (device globals — allocation-free)
static __device__ float g_q[B_ * CQ_ * L_];        // 4 MB
static __device__ float g_k[B_ * CQ_ * L_];        // 4 MB
static __device__ float g_v[B_ * C_ * L_];         // 33.5 MB
static __device__ float g_s[B_ * L_ * L_];         // 134 MB (scores, then beta in place)

// ---------------------------------------------------------------------------
// Conv-as-implicit-GEMM: out[b, m, l] = sum_{c,t} W[m, c, t] * x[b, c, l+t-1]
// A = W  [M, 1536] row-major (c*3+t is exactly the flat layout of W[o][c][t])
// B = im2col(x) [1536, 128] tile, generated on the fly with zero-padding.
// Block tile 128x128, K-tile 16, 256 threads, 8x8 micro-tile.
// Rows >= Msplit come from W1/out1 (used to stack Wq|Wk into one launch).
// ---------------------------------------------------------------------------
__device__ __forceinline__ void conv_gemm_body(
    const float* __restrict__ x,
    const float* __restrict__ W0, const float* __restrict__ W1,
    float* __restrict__ out0, float* __restrict__ out1,
    int Msplit, int ostride)
{
    __shared__ float As[16][128];
    __shared__ float Bs[16][128];

    const int b  = blockIdx.z;
    const int l0 = blockIdx.x * 128;
    const int m0 = blockIdx.y * 128;
    const int tid = threadIdx.x;

    // A-load mapping: 2 threads per row, 8 consecutive k each
    const int mloc = tid >> 1;
    const int half = tid & 1;
    const int mg   = m0 + mloc;
    const float* Arow = (mg < Msplit) ? (W0 + mg * KK_)
                                      : (W1 + (mg - Msplit) * KK_);
    Arow += half * 8;

    // B-load mapping: 16 threads per k-row, 8 consecutive n each
    const int kr = tid >> 4;
    const int n0 = (tid & 15) * 8;
    const float* xb = x + b * C_ * L_;

    const int tm = (tid >> 4) * 8;
    const int tn = (tid & 15) * 8;

    float acc[8][8];
#pragma unroll
    for (int i = 0; i < 8; i++)
#pragma unroll
        for (int j = 0; j < 8; j++) acc[i][j] = 0.f;

    for (int k0 = 0; k0 < KK_; k0 += 16) {
        // --- load A tile (transpose into As[k][m]) ---
        float4 a0 = *(const float4*)(Arow + k0);
        float4 a1 = *(const float4*)(Arow + k0 + 4);
        As[half * 8 + 0][mloc] = a0.x;
        As[half * 8 + 1][mloc] = a0.y;
        As[half * 8 + 2][mloc] = a0.z;
        As[half * 8 + 3][mloc] = a0.w;
        As[half * 8 + 4][mloc] = a1.x;
        As[half * 8 + 5][mloc] = a1.y;
        As[half * 8 + 6][mloc] = a1.z;
        As[half * 8 + 7][mloc] = a1.w;

        // --- load B tile (implicit im2col with zero padding) ---
        const int kk = k0 + kr;
        const int c  = kk / 3;
        const int t  = kk - c * 3;
        const float* xrow = xb + c * L_;
        const int base = l0 + n0 + t - 1;
#pragma unroll
        for (int j = 0; j < 8; j++) {
            const int gl = base + j;
            Bs[kr][n0 + j] = (gl >= 0 && gl < L_) ? xrow[gl] : 0.f;
        }
        __syncthreads();

#pragma unroll
        for (int kk2 = 0; kk2 < 16; kk2++) {
            float af[8], bf[8];
#pragma unroll
            for (int i = 0; i < 8; i++) af[i] = As[kk2][tm + i];
#pragma unroll
            for (int j = 0; j < 8; j++) bf[j] = Bs[kk2][tn + j];
#pragma unroll
            for (int i = 0; i < 8; i++)
#pragma unroll
                for (int j = 0; j < 8; j++)
                    acc[i][j] = fmaf(af[i], bf[j], acc[i][j]);
        }
        __syncthreads();
    }

    // --- epilogue ---
#pragma unroll
    for (int i = 0; i < 8; i++) {
        const int m = m0 + tm + i;
        float* orow = (m < Msplit) ? (out0 + b * ostride + m * L_)
                                   : (out1 + b * ostride + (m - Msplit) * L_);
        float4 s0 = make_float4(acc[i][0], acc[i][1], acc[i][2], acc[i][3]);
        float4 s1 = make_float4(acc[i][4], acc[i][5], acc[i][6], acc[i][7]);
        *(float4*)(orow + l0 + tn)     = s0;
        *(float4*)(orow + l0 + tn + 4) = s1;
    }
}

__global__ __launch_bounds__(256, 2) void conv_qk_kernel(
    const float* __restrict__ x, const float* __restrict__ Wq,
    const float* __restrict__ Wk)
{
    conv_gemm_body(x, Wq, Wk, g_q, g_k, CQ_, CQ_ * L_);
}

__global__ __launch_bounds__(256, 2) void conv_v_kernel(
    const float* __restrict__ x, const float* __restrict__ Wv)
{
    conv_gemm_body(x, Wv, Wv, g_v, g_v, 1 << 30, C_ * L_);
}

// ---------------------------------------------------------------------------
// scores[b, i, j] = sum_c q[b, c, i] * k[b, c, j]     (K = 64)
// Both operands are k-major in memory already (q[c][i], k[c][j]) ->
// contiguous float4 loads straight into As[k][m] / Bs[k][n].
// ---------------------------------------------------------------------------
__global__ __launch_bounds__(256, 2) void scores_kernel()
{
    __shared__ float As[16][128];
    __shared__ float Bs[16][128];

    const int b  = blockIdx.z;
    const int j0 = blockIdx.x * 128;
    const int i0 = blockIdx.y * 128;
    const int tid = threadIdx.x;

    const int kc = tid >> 4;           // k-row within tile
    const int p0 = (tid & 15) * 8;     // position within row
    const int tm = (tid >> 4) * 8;
    const int tn = (tid & 15) * 8;

    const float* qb = g_q + b * CQ_ * L_;
    const float* kb = g_k + b * CQ_ * L_;

    float acc[8][8];
#pragma unroll
    for (int i = 0; i < 8; i++)
#pragma unroll
        for (int j = 0; j < 8; j++) acc[i][j] = 0.f;

    for (int c0 = 0; c0 < CQ_; c0 += 16) {
        const float* qrow = qb + (c0 + kc) * L_ + i0 + p0;
        const float* krow = kb + (c0 + kc) * L_ + j0 + p0;
        *(float4*)&As[kc][p0]     = *(const float4*)(qrow);
        *(float4*)&As[kc][p0 + 4] = *(const float4*)(qrow + 4);
        *(float4*)&Bs[kc][p0]     = *(const float4*)(krow);
        *(float4*)&Bs[kc][p0 + 4] = *(const float4*)(krow + 4);
        __syncthreads();

#pragma unroll
        for (int kk2 = 0; kk2 < 16; kk2++) {
            float af[8], bf[8];
#pragma unroll
            for (int i = 0; i < 8; i++) af[i] = As[kk2][tm + i];
#pragma unroll
            for (int j = 0; j < 8; j++) bf[j] = Bs[kk2][tn + j];
#pragma unroll
            for (int i = 0; i < 8; i++)
#pragma unroll
                for (int j = 0; j < 8; j++)
                    acc[i][j] = fmaf(af[i], bf[j], acc[i][j]);
        }
        __syncthreads();
    }

    float* sb = g_s + b * L_ * L_;
#pragma unroll
    for (int i = 0; i < 8; i++) {
        float* orow = sb + (i0 + tm + i) * L_ + j0 + tn;
        float4 s0 = make_float4(acc[i][0], acc[i][1], acc[i][2], acc[i][3]);
        float4 s1 = make_float4(acc[i][4], acc[i][5], acc[i][6], acc[i][7]);
        *(float4*)(orow)     = s0;
        *(float4*)(orow + 4) = s1;
    }
}

// ---------------------------------------------------------------------------
// In-place softmax over axis i (dim 1) of g_s[b, i, j].
// Warps span j -> fully coalesced. 4 i-groups per column, smem reduce.
// ---------------------------------------------------------------------------
__global__ __launch_bounds__(256) void softmax_kernel()
{
    __shared__ float redm[256];
    __shared__ float reds[256];

    const int b  = blockIdx.y;
    const int j0 = blockIdx.x * 64;
    const int tid = threadIdx.x;
    const int jj = tid & 63;
    const int ig = tid >> 6;           // 0..3

    float* sb = g_s + b * L_ * L_ + j0 + jj;

    // pass 1: online max + sum(exp)
    float m = -1e30f, s = 0.f;
    for (int i = ig; i < L_; i += 4) {
        const float v = sb[i * L_];
        const float nm = fmaxf(m, v);
        s = s * __expf(m - nm) + __expf(v - nm);
        m = nm;
    }
    redm[tid] = m;
    reds[tid] = s;
    __syncthreads();

    float M = -1e30f, S = 0.f;
#pragma unroll
    for (int g = 0; g < 4; g++) {
        const float mm = redm[g * 64 + jj];
        const float ss = reds[g * 64 + jj];
        const float nm = fmaxf(M, mm);
        S = S * __expf(M - nm) + ss * __expf(mm - nm);
        M = nm;
    }
    const float inv = 1.f / S;

    // pass 2: normalize in place
    for (int i = ig; i < L_; i += 4) {
        const float v = sb[i * L_];
        sb[i * L_] = __expf(v - M) * inv;
    }
}

// ---------------------------------------------------------------------------
// out[b, c, j] = gamma * sum_l v[b, c, l] * beta[b, l, j]
// A = v [512, 2048] row-major, B = beta [2048, 2048] row-major. K = 2048.
// ---------------------------------------------------------------------------
__global__ __launch_bounds__(256, 2) void out_gemm_kernel(
    const float* __restrict__ gamma, float* __restrict__ out)
{
    __shared__ float As[16][128];
    __shared__ float Bs[16][128];

    const int b  = blockIdx.z;
    const int j0 = blockIdx.x * 128;
    const int c0 = blockIdx.y * 128;
    const int tid = threadIdx.x;

    const int mloc = tid >> 1;
    const int half = tid & 1;
    const float* Arow = g_v + b * C_ * L_ + (c0 + mloc) * L_ + half * 8;

    const int kr = tid >> 4;
    const int n0 = (tid & 15) * 8;
    const float* Bb = g_s + b * L_ * L_ + j0 + n0;

    const int tm = (tid >> 4) * 8;
    const int tn = (tid & 15) * 8;

    float acc[8][8];
#pragma unroll
    for (int i = 0; i < 8; i++)
#pragma unroll
        for (int j = 0; j < 8; j++) acc[i][j] = 0.f;

    for (int k0 = 0; k0 < L_; k0 += 16) {
        float4 a0 = *(const float4*)(Arow + k0);
        float4 a1 = *(const float4*)(Arow + k0 + 4);
        As[half * 8 + 0][mloc] = a0.x;
        As[half * 8 + 1][mloc] = a0.y;
        As[half * 8 + 2][mloc] = a0.z;
        As[half * 8 + 3][mloc] = a0.w;
        As[half * 8 + 4][mloc] = a1.x;
        As[half * 8 + 5][mloc] = a1.y;
        As[half * 8 + 6][mloc] = a1.z;
        As[half * 8 + 7][mloc] = a1.w;

        const float* brow = Bb + (k0 + kr) * L_;
        *(float4*)&Bs[kr][n0]     = *(const float4*)(brow);
        *(float4*)&Bs[kr][n0 + 4] = *(const float4*)(brow + 4);
        __syncthreads();

#pragma unroll
        for (int kk2 = 0; kk2 < 16; kk2++) {
            float af[8], bf[8];
#pragma unroll
            for (int i = 0; i < 8; i++) af[i] = As[kk2][tm + i];
#pragma unroll
            for (int j = 0; j < 8; j++) bf[j] = Bs[kk2][tn + j];
#pragma unroll
            for (int i = 0; i < 8; i++)
#pragma unroll
                for (int j = 0; j < 8; j++)
                    acc[i][j] = fmaf(af[i], bf[j], acc[i][j]);
        }
        __syncthreads();
    }

    const float g = __ldg(gamma);
#pragma unroll
    for (int i = 0; i < 8; i++) {
        float* orow = out + b * C_ * L_ + (c0 + tm + i) * L_ + j0 + tn;
        float4 s0 = make_float4(g * acc[i][0], g * acc[i][1],
                                g * acc[i][2], g * acc[i][3]);
        float4 s1 = make_float4(g * acc[i][4], g * acc[i][5],
                                g * acc[i][6], g * acc[i][7]);
        *(float4*)(orow)     = s0;
        *(float4*)(orow + 4) = s1;
    }
}

// ---------------------------------------------------------------------------
extern "C" void kernel_launch(void* const* d_in, const int* in_sizes, int n_in,
                              void* d_out, int out_size)
{
    const float* x     = (const float*)d_in[0];
    const float* Wq    = (const float*)d_in[1];
    const float* Wk    = (const float*)d_in[2];
    const float* Wv    = (const float*)d_in[3];
    const float* gamma = (const float*)d_in[4];
    float* out = (float*)d_out;

    dim3 blk(256);

    // 1. q & k convs (Wq stacked with Wk into one 128-row GEMM)
    conv_qk_kernel<<<dim3(L_ / 128, 1, B_), blk>>>(x, Wq, Wk);

    // 2. v conv
    conv_v_kernel<<<dim3(L_ / 128, C_ / 128, B_), blk>>>(x, Wv);

    // 3. scores = q^T k
    scores_kernel<<<dim3(L_ / 128, L_ / 128, B_), blk>>>();

    // 4. softmax over axis i (in place)
    softmax_kernel<<<dim3(L_ / 64, B_), blk>>>();

    // 5. out = gamma * v @ beta
    out_gemm_kernel<<<dim3(L_ / 128, C_ / 128, B_), blk>>>(gamma, out);
}